// round 4
// baseline (speedup 1.0000x reference)
#include <cuda_runtime.h>

#define B 64
#define H 768
#define E 128

#define NRED 512                 // core-reduce blocks, 16 KB each
#define KS 12                    // GEMM k-splits (K chunk = 64 floats)
#define NGEMM (KS * 4 * 2)       // 12 ks x 4 echunk x 2 bgroup = 96
#define GRID (NRED + NGEMM)      // 608
#define NCOMB 16                 // combiner blocks (bid 0..15), 4 b-rows each

__device__ float g_S2p[NRED];            // core partials (4 per leading index i)
__device__ float g_P[3][KS][B][E];       // [mat][ks][b][e] gemm partials
__device__ unsigned g_arrive;            // zero-init; self-resetting each launch
__device__ unsigned g_done2;

__global__ void __launch_bounds__(256, 3)
k_all(const float* __restrict__ core,
      const float* __restrict__ hs, const float* __restrict__ rs,
      const float* __restrict__ ts, const float* __restrict__ we,
      const float* __restrict__ wr, const float* __restrict__ be,
      const float* __restrict__ br, float* __restrict__ out) {
    __shared__ float4 s_src[3][32][17];  // gemm src tiles (pad 17 -> conflict-free)
    __shared__ float4 s_w[2][32][17];    // gemm We/Wr tiles

    const int bid = blockIdx.x;
    const int tid = threadIdx.x;

    if (bid < NRED) {
        // ---------------- core reduction: 16 KB chunk, MLP=4 ----------------
        const float4* src = reinterpret_cast<const float4*>(core) + (size_t)bid * 1024;
        const float4 v0 = __ldg(src + tid);
        const float4 v1 = __ldg(src + tid + 256);
        const float4 v2 = __ldg(src + tid + 512);
        const float4 v3 = __ldg(src + tid + 768);
        float s = (((v0.x + v0.y) + (v0.z + v0.w)) + ((v1.x + v1.y) + (v1.z + v1.w)))
                + (((v2.x + v2.y) + (v2.z + v2.w)) + ((v3.x + v3.y) + (v3.z + v3.w)));
#pragma unroll
        for (int o = 16; o > 0; o >>= 1) s += __shfl_xor_sync(0xffffffffu, s, o);
        float* ws = reinterpret_cast<float*>(s_w);
        if ((tid & 31) == 0) ws[tid >> 5] = s;
        __syncthreads();
        if (tid == 0) {
            float tot = 0.f;
#pragma unroll
            for (int w = 0; w < 8; w++) tot += ws[w];
            g_S2p[bid] = tot;
        }
    } else {
        // ---------------- triple GEMM: 32b x 32e x 64k tile, 2b x 2e/thread -
        const int lin = bid - NRED;
        const int ks = lin % KS, ec = (lin / KS) & 3, bg = lin / (KS * 4);
        const int b0 = bg * 32, e0 = ec * 32;
        const int c0 = ks * 16;  // float4 column offset (64-float K chunk)

        const float4* g0 = reinterpret_cast<const float4*>(hs);
        const float4* g1 = reinterpret_cast<const float4*>(rs);
        const float4* g2 = reinterpret_cast<const float4*>(ts);
        const float4* gwe = reinterpret_cast<const float4*>(we);
        const float4* gwr = reinterpret_cast<const float4*>(wr);

#pragma unroll
        for (int i = tid; i < 512; i += 256) {
            const int row = i >> 4, c4 = i & 15;
            const size_t gidx = (size_t)(b0 + row) * 192 + c0 + c4;
            s_src[0][row][c4] = g0[gidx];
            s_src[1][row][c4] = g1[gidx];
            s_src[2][row][c4] = g2[gidx];
        }
#pragma unroll
        for (int i = tid; i < 512; i += 256) {
            const int row = i >> 4, c4 = i & 15;
            const size_t gidx = (size_t)(e0 + row) * 192 + c0 + c4;
            s_w[0][row][c4] = gwe[gidx];
            s_w[1][row][c4] = gwr[gidx];
        }
        __syncthreads();

        const int te = tid & 15;   // e pair: (e0+te, e0+te+16)
        const int tb = tid >> 4;   // b pair: (b0+2tb, b0+2tb+1)
        const int ra = 2 * tb, rb = ra + 1;

        float h00 = 0.f, h01 = 0.f, h10 = 0.f, h11 = 0.f;
        float r00 = 0.f, r01 = 0.f, r10 = 0.f, r11 = 0.f;
        float t00 = 0.f, t01 = 0.f, t10 = 0.f, t11 = 0.f;
#pragma unroll
        for (int k4 = 0; k4 < 16; k4++) {
            const float4 weA = s_w[0][te][k4];
            const float4 weB = s_w[0][te + 16][k4];
            const float4 wrA = s_w[1][te][k4];
            const float4 wrB = s_w[1][te + 16][k4];
            const float4 ah0 = s_src[0][ra][k4], ah1 = s_src[0][rb][k4];
            const float4 ar0 = s_src[1][ra][k4], ar1 = s_src[1][rb][k4];
            const float4 at0 = s_src[2][ra][k4], at1 = s_src[2][rb][k4];

            h00 += weA.x * ah0.x + weA.y * ah0.y + weA.z * ah0.z + weA.w * ah0.w;
            h01 += weB.x * ah0.x + weB.y * ah0.y + weB.z * ah0.z + weB.w * ah0.w;
            h10 += weA.x * ah1.x + weA.y * ah1.y + weA.z * ah1.z + weA.w * ah1.w;
            h11 += weB.x * ah1.x + weB.y * ah1.y + weB.z * ah1.z + weB.w * ah1.w;
            r00 += wrA.x * ar0.x + wrA.y * ar0.y + wrA.z * ar0.z + wrA.w * ar0.w;
            r01 += wrB.x * ar0.x + wrB.y * ar0.y + wrB.z * ar0.z + wrB.w * ar0.w;
            r10 += wrA.x * ar1.x + wrA.y * ar1.y + wrA.z * ar1.z + wrA.w * ar1.w;
            r11 += wrB.x * ar1.x + wrB.y * ar1.y + wrB.z * ar1.z + wrB.w * ar1.w;
            t00 += weA.x * at0.x + weA.y * at0.y + weA.z * at0.z + weA.w * at0.w;
            t01 += weB.x * at0.x + weB.y * at0.y + weB.z * at0.z + weB.w * at0.w;
            t10 += weA.x * at1.x + weA.y * at1.y + weA.z * at1.z + weA.w * at1.w;
            t11 += weB.x * at1.x + weB.y * at1.y + weB.z * at1.z + weB.w * at1.w;
        }

        const int bA = b0 + ra, bB = b0 + rb;
        const int eA = e0 + te, eB = e0 + te + 16;
        g_P[0][ks][bA][eA] = h00;  g_P[0][ks][bA][eB] = h01;
        g_P[0][ks][bB][eA] = h10;  g_P[0][ks][bB][eB] = h11;
        g_P[1][ks][bA][eA] = r00;  g_P[1][ks][bA][eB] = r01;
        g_P[1][ks][bB][eA] = r10;  g_P[1][ks][bB][eB] = r11;
        g_P[2][ks][bA][eA] = t00;  g_P[2][ks][bA][eB] = t01;
        g_P[2][ks][bB][eA] = t10;  g_P[2][ks][bB][eB] = t11;
    }

    // ---------------- arrive (all blocks) --------------------------------
    __threadfence();
    __syncthreads();
    if (tid == 0) atomicAdd(&g_arrive, 1u);

    if (bid >= NCOMB) return;

    // ---------------- combine (blocks 0..15, 4 b-rows each) --------------
    if (tid == 0) {
        volatile unsigned* p = &g_arrive;
        while (*p < GRID) __nanosleep(64);
    }
    __syncthreads();
    __threadfence();

    float* sc = reinterpret_cast<float*>(s_src);  // cross-warp scratch
#pragma unroll
    for (int pass = 0; pass < 2; pass++) {
        const int g = tid >> 7;                 // group 0/1 within block
        const int b = bid * 4 + pass * 2 + g;
        const int e = tid & 127;

        float h = 0.f, r = 0.f, t = 0.f;
#pragma unroll
        for (int k = 0; k < KS; k++) {
            h += g_P[0][k][b][e];
            r += g_P[1][k][b][e];
            t += g_P[2][k][b][e];
        }
        const float bias_e = be[e], bias_r = br[e];
        const float s2 = (g_S2p[4 * e] + g_S2p[4 * e + 1])
                       + (g_S2p[4 * e + 2] + g_S2p[4 * e + 3]);
        float v = (h + bias_e) * (r + bias_r) * (t + bias_e) * s2;
#pragma unroll
        for (int o = 16; o > 0; o >>= 1) v += __shfl_xor_sync(0xffffffffu, v, o);
        if ((tid & 31) == 0) sc[tid >> 5] = v;
        __syncthreads();
        if ((tid & 127) == 0) {
            const int w0 = g * 4;
            out[b] = -((sc[w0] + sc[w0 + 1]) + (sc[w0 + 2] + sc[w0 + 3]));
        }
        __syncthreads();
    }

    if (tid == 0) {
        const unsigned t = atomicAdd(&g_done2, 1u);
        if (t == NCOMB - 1) {        // last combiner resets for next replay
            g_arrive = 0u;
            __threadfence();
            g_done2 = 0u;
        }
    }
}

// ---------------------------------------------------------------------------
extern "C" void kernel_launch(void* const* d_in, const int* in_sizes, int n_in,
                              void* d_out, int out_size) {
    const float* head = (const float*)d_in[0];
    const float* rel  = (const float*)d_in[1];
    const float* tail = (const float*)d_in[2];
    const float* We   = (const float*)d_in[3];
    const float* be   = (const float*)d_in[4];
    const float* Wr   = (const float*)d_in[5];
    const float* br   = (const float*)d_in[6];
    const float* core = (const float*)d_in[7];
    float* out = (float*)d_out;

    k_all<<<GRID, 256>>>(core, head, rel, tail, We, Wr, be, br, out);
}

// round 5
// speedup vs baseline: 1.1737x; 1.1737x over previous
#include <cuda_runtime.h>

#define B 64
#define H 768
#define E 128

#define KS 12                     // GEMM k-splits (K chunk = 64 floats)
#define NGEMM (KS * 8 * 2)        // 192 GEMM blocks, bids [0,192)  — launch FIRST
#define NRED 512                  // reduce blocks, bids [192,704), 16 KB each
#define GRID (NGEMM + NRED)       // 704
#define NCOMB 16                  // combiners = last 16 blocks (bid >= 688)

__device__ float g_S2p[NRED];          // core partials (4 per leading index i)
__device__ float g_P[3][KS][B][E];     // [mat][ks][b][e] gemm partials
__device__ unsigned g_arrive;          // zero-init; self-resetting per launch
__device__ unsigned g_done2;

__global__ void __launch_bounds__(256)
k_all(const float* __restrict__ core,
      const float* __restrict__ hs, const float* __restrict__ rs,
      const float* __restrict__ ts, const float* __restrict__ we,
      const float* __restrict__ wr, const float* __restrict__ be,
      const float* __restrict__ br, float* __restrict__ out) {
    __shared__ float4 s_src[3][32][18];  // gemm src tiles (swizzled)
    __shared__ float4 s_w[2][16][18];    // gemm We/Wr tiles

    const int bid = blockIdx.x;
    const int tid = threadIdx.x;

    if (bid < NGEMM) {
        // ------- triple GEMM (round-2 proven config): 32b x 16e x 64k tile --
        const int ks = bid % KS, ec = (bid / KS) & 7, bg = bid / (KS * 8);
        const int b0 = bg * 32, e0 = ec * 16;
        const int c0 = ks * 16;  // float4 col offset (64-float K chunk)

        const float4* g0 = reinterpret_cast<const float4*>(hs);
        const float4* g1 = reinterpret_cast<const float4*>(rs);
        const float4* g2 = reinterpret_cast<const float4*>(ts);
#pragma unroll
        for (int i = tid; i < 512; i += 256) {
            const int row = i >> 4, c4 = i & 15;
            const size_t gidx = (size_t)(b0 + row) * 192 + c0 + c4;
            const int sc = c4 ^ (row & 7);
            s_src[0][row][sc] = g0[gidx];
            s_src[1][row][sc] = g1[gidx];
            s_src[2][row][sc] = g2[gidx];
        }
        {
            const int row = tid >> 4, c4 = tid & 15;
            const size_t gidx = (size_t)(e0 + row) * 192 + c0 + c4;
            const int sc = c4 ^ (row & 7);
            s_w[0][row][sc] = reinterpret_cast<const float4*>(we)[gidx];
            s_w[1][row][sc] = reinterpret_cast<const float4*>(wr)[gidx];
        }
        __syncthreads();

        const int te = tid & 15;   // e within tile
        const int tb = tid >> 4;   // b pair within tile
        const int ba = 2 * tb, bb = ba + 1;

        float h0 = 0.f, h1 = 0.f, r0 = 0.f, r1 = 0.f, t0 = 0.f, t1 = 0.f;
#pragma unroll
        for (int k4 = 0; k4 < 16; k4++) {
            const float4 vwe = s_w[0][te][k4 ^ (te & 7)];
            const float4 vwr = s_w[1][te][k4 ^ (te & 7)];
            const int sa = k4 ^ (ba & 7), sb = k4 ^ (bb & 7);
            float4 a, c;
            a = s_src[0][ba][sa]; c = s_src[0][bb][sb];
            h0 += vwe.x * a.x + vwe.y * a.y + vwe.z * a.z + vwe.w * a.w;
            h1 += vwe.x * c.x + vwe.y * c.y + vwe.z * c.z + vwe.w * c.w;
            a = s_src[1][ba][sa]; c = s_src[1][bb][sb];
            r0 += vwr.x * a.x + vwr.y * a.y + vwr.z * a.z + vwr.w * a.w;
            r1 += vwr.x * c.x + vwr.y * c.y + vwr.z * c.z + vwr.w * c.w;
            a = s_src[2][ba][sa]; c = s_src[2][bb][sb];
            t0 += vwe.x * a.x + vwe.y * a.y + vwe.z * a.z + vwe.w * a.w;
            t1 += vwe.x * c.x + vwe.y * c.y + vwe.z * c.z + vwe.w * c.w;
        }

        const int bga = b0 + ba, bgb = b0 + bb;
        const int e = e0 + te;
        g_P[0][ks][bga][e] = h0;  g_P[0][ks][bgb][e] = h1;
        g_P[1][ks][bga][e] = r0;  g_P[1][ks][bgb][e] = r1;
        g_P[2][ks][bga][e] = t0;  g_P[2][ks][bgb][e] = t1;
    } else {
        // ------- core reduction: 16 KB chunk, 4 explicit loads (MLP=4) ------
        const int rb = bid - NGEMM;
        const float4* src = reinterpret_cast<const float4*>(core) + (size_t)rb * 1024;
        const float4 v0 = __ldg(src + tid);
        const float4 v1 = __ldg(src + tid + 256);
        const float4 v2 = __ldg(src + tid + 512);
        const float4 v3 = __ldg(src + tid + 768);
        float s = (((v0.x + v0.y) + (v0.z + v0.w)) + ((v1.x + v1.y) + (v1.z + v1.w)))
                + (((v2.x + v2.y) + (v2.z + v2.w)) + ((v3.x + v3.y) + (v3.z + v3.w)));
#pragma unroll
        for (int o = 16; o > 0; o >>= 1) s += __shfl_xor_sync(0xffffffffu, s, o);
        float* ws = reinterpret_cast<float*>(s_w);
        if ((tid & 31) == 0) ws[tid >> 5] = s;
        __syncthreads();
        if (tid == 0) {
            float tot = 0.f;
#pragma unroll
            for (int w = 0; w < 8; w++) tot += ws[w];
            g_S2p[rb] = tot;
        }
    }

    // ---------------- arrive (every block) -------------------------------
    __threadfence();
    __syncthreads();
    if (tid == 0) atomicAdd(&g_arrive, 1u);

    if (bid < GRID - NCOMB) return;

    // ---------------- combine (last 16 blocks, 4 b-rows each) ------------
    if (tid == 0) {
        volatile unsigned* p = &g_arrive;
        while (*p < GRID) __nanosleep(32);
    }
    __syncthreads();
    __threadfence();

    const int cb = bid - (GRID - NCOMB);          // 0..15
    float* sc = reinterpret_cast<float*>(s_src);  // cross-warp scratch
#pragma unroll
    for (int pass = 0; pass < 2; pass++) {
        const int g = tid >> 7;                   // row group 0/1 in block
        const int b = cb * 4 + pass * 2 + g;
        const int e = tid & 127;

        float h = 0.f, r = 0.f, t = 0.f;
#pragma unroll
        for (int k = 0; k < KS; k++) {
            h += g_P[0][k][b][e];
            r += g_P[1][k][b][e];
            t += g_P[2][k][b][e];
        }
        const float bias_e = be[e], bias_r = br[e];
        const float s2 = (g_S2p[4 * e] + g_S2p[4 * e + 1])
                       + (g_S2p[4 * e + 2] + g_S2p[4 * e + 3]);
        float v = (h + bias_e) * (r + bias_r) * (t + bias_e) * s2;
#pragma unroll
        for (int o = 16; o > 0; o >>= 1) v += __shfl_xor_sync(0xffffffffu, v, o);
        if ((tid & 31) == 0) sc[tid >> 5] = v;
        __syncthreads();
        if ((tid & 127) == 0) {
            const int w0 = g * 4;
            out[b] = -((sc[w0] + sc[w0 + 1]) + (sc[w0 + 2] + sc[w0 + 3]));
        }
        __syncthreads();
    }

    if (tid == 0) {
        const unsigned t = atomicAdd(&g_done2, 1u);
        if (t == NCOMB - 1) {          // last combiner resets for next replay
            g_arrive = 0u;
            __threadfence();
            g_done2 = 0u;
        }
    }
}

// ---------------------------------------------------------------------------
extern "C" void kernel_launch(void* const* d_in, const int* in_sizes, int n_in,
                              void* d_out, int out_size) {
    const float* head = (const float*)d_in[0];
    const float* rel  = (const float*)d_in[1];
    const float* tail = (const float*)d_in[2];
    const float* We   = (const float*)d_in[3];
    const float* be   = (const float*)d_in[4];
    const float* Wr   = (const float*)d_in[5];
    const float* br   = (const float*)d_in[6];
    const float* core = (const float*)d_in[7];
    float* out = (float*)d_out;

    k_all<<<GRID, 256>>>(core, head, rel, tail, We, Wr, be, br, out);
}